// round 12
// baseline (speedup 1.0000x reference)
#include <cuda_runtime.h>

#define N_NODES 100000
#define N_EDGES 1600000
#define IN_DIM 64
#define HID_DIM 128
#define OUT_DIM 40
#define CAP 80
#define TILE 128
#define NTILES ((N_NODES + TILE - 1) / TILE)   // 782
#define ASTRIDE 132                 // [k][node] tile stride (128 + 4 pad)
#define WST 132                     // transposed weight row stride (128 k + pad)

// ---------------- scratch ----------------
__device__ __align__(16) float g_agg1[N_NODES * IN_DIM];
__device__ __align__(16) float g_t[N_NODES * OUT_DIM];
__device__ int g_deg[N_NODES];
__device__ int g_csr[N_NODES * CAP];
__device__ int g_is64;

typedef unsigned long long ull;
__device__ __forceinline__ ull f2pack(float lo, float hi) {
    ull r; asm("mov.b64 %0, {%1,%2};" : "=l"(r) : "f"(lo), "f"(hi)); return r;
}
__device__ __forceinline__ void f2unpack(ull v, float& lo, float& hi) {
    asm("mov.b64 {%0,%1}, %2;" : "=f"(lo), "=f"(hi) : "l"(v));
}
__device__ __forceinline__ ull fma2(ull a, ull b, ull c) {
    ull d; asm("fma.rn.f32x2 %0, %1, %2, %3;" : "=l"(d)
               : "l"(a), "l"(b), "l"(c)); return d;
}

// ---------------- K-prep: zero degrees + dtype detect -----------------------
__global__ void k_prep(const long long* __restrict__ ei) {
    int i = blockIdx.x * blockDim.x + threadIdx.x;
    if (i < N_NODES) g_deg[i] = 0;
    if (blockIdx.x == 0) {
        long long v = ei[threadIdx.x];
        int ok = (v >= 0 && v < N_NODES);
        int all = __syncthreads_and(ok);
        if (threadIdx.x == 0) g_is64 = all;
    }
}

// ---------------- K-build ----------------------------------------------------
__global__ void k_build(const void* __restrict__ ei) {
    int e = blockIdx.x * blockDim.x + threadIdx.x;
    if (e >= N_EDGES) return;
    int s, d;
    if (g_is64) {
        s = (int)((const long long*)ei)[e];
        d = (int)((const long long*)ei)[N_EDGES + e];
    } else {
        s = ((const int*)ei)[e];
        d = ((const int*)ei)[N_EDGES + e];
    }
    int slot = atomicAdd(&g_deg[d], 1);
    if (slot < CAP) g_csr[d * CAP + slot] = s;
}

// ---------------- K-gather1 --------------------------------------------------
__global__ void k_gather1(const float* __restrict__ x) {
    int w = (blockIdx.x * blockDim.x + threadIdx.x) >> 5;
    if (w >= N_NODES) return;
    int lane = threadIdx.x & 31;
    int p = lane >> 4;
    int c = lane & 15;
    int deg = min(g_deg[w], CAP);
    const int* row = g_csr + (size_t)w * CAP;

    float4 acc = make_float4(0.f, 0.f, 0.f, 0.f);
    if (p == 0)
        acc = *reinterpret_cast<const float4*>(x + (size_t)w * IN_DIM + c * 4);

    #pragma unroll 4
    for (int j = 0; j < deg; j += 2) {
        if (j + p < deg) {
            int s = row[j + p];
            float4 v = *reinterpret_cast<const float4*>(
                x + (size_t)s * IN_DIM + c * 4);
            acc.x += v.x; acc.y += v.y; acc.z += v.z; acc.w += v.w;
        }
    }
    acc.x += __shfl_xor_sync(0xffffffffu, acc.x, 16);
    acc.y += __shfl_xor_sync(0xffffffffu, acc.y, 16);
    acc.z += __shfl_xor_sync(0xffffffffu, acc.z, 16);
    acc.w += __shfl_xor_sync(0xffffffffu, acc.w, 16);
    if (p == 0)
        *reinterpret_cast<float4*>(g_agg1 + (size_t)w * IN_DIM + c * 4) = acc;
}

// ---------------- K2: fused MLP (TILE=128, 1024 thr, 2col x 8node) ----------
// smem layout (floats); A aliases the low half of H (A dead after layer 1).
constexpr int S_W2T = 0;                         // 128*132 = 16896
constexpr int S_W3T = S_W2T + HID_DIM * WST;     // +5280
constexpr int S_B1  = S_W3T + OUT_DIM * WST;     // +128
constexpr int S_B2  = S_B1 + HID_DIM;            // +128
constexpr int S_T   = S_B2 + HID_DIM;            // 128*132 = 16896
constexpr int S_H   = S_T + HID_DIM * ASTRIDE;   // 128*132 = 16896
constexpr int S_A   = S_H;                       // alias: 64*132 = 8448
constexpr int S_TOTAL = S_H + HID_DIM * ASTRIDE; // 56224 floats
constexpr int SMEM_BYTES = S_TOTAL * 4;          // 224896 B

__global__ void __launch_bounds__(1024, 1)
k_mlp(const float* __restrict__ W1, const float* __restrict__ b1,
      const float* __restrict__ W2, const float* __restrict__ b2,
      const float* __restrict__ W3) {
    extern __shared__ float sm[];
    int tid = threadIdx.x;

    // stage W2, W3 TRANSPOSED: Wt[c][k] = W[k][c]; biases
    for (int i = tid; i < HID_DIM * HID_DIM; i += 1024) {
        int k = i >> 7, c = i & 127;
        sm[S_W2T + c * WST + k] = W2[i];
    }
    for (int i = tid; i < HID_DIM * OUT_DIM; i += 1024) {
        int k = i / OUT_DIM, c = i % OUT_DIM;
        sm[S_W3T + c * WST + k] = W3[i];
    }
    if (tid < HID_DIM) { sm[S_B1 + tid] = b1[tid]; sm[S_B2 + tid] = b2[tid]; }

    const int cp  = tid & 63;          // cols cp, cp+64
    const int nb  = (tid >> 6) * 8;    // 8-node group base (0..120)
    const int pc  = tid % 40;          // proj column
    const int pnb = (tid / 40) * 8;    // proj node base (0..120)
    const bool pact = tid < 640;

    // stage tile 0 into A (transposed [k][n]); 2048 items
    int g = blockIdx.x;
    for (int it = tid; it < 2048; it += 1024) {
        int n = it >> 4, k4 = (it & 15) * 4;
        int node = g * TILE + n;
        float4 v = (node < N_NODES)
            ? *reinterpret_cast<const float4*>(g_agg1 + (size_t)node * IN_DIM + k4)
            : make_float4(0.f, 0.f, 0.f, 0.f);
        sm[S_A + (k4 + 0) * ASTRIDE + n] = v.x;
        sm[S_A + (k4 + 1) * ASTRIDE + n] = v.y;
        sm[S_A + (k4 + 2) * ASTRIDE + n] = v.z;
        sm[S_A + (k4 + 3) * ASTRIDE + n] = v.w;
    }

    for (; g < NTILES; g += gridDim.x) {
        int base = g * TILE;
        __syncthreads();                       // A + weights ready

        // ---- layer 1: 64 -> 128, relu. W1 from global (L1-resident). ----
        {
            float bb0 = sm[S_B1 + cp], bb1v = sm[S_B1 + cp + 64];
            ull a0 = f2pack(bb0, bb0), a1 = a0, a2 = a0, a3 = a0;
            ull a4 = f2pack(bb1v, bb1v), a5 = a4, a6 = a4, a7 = a4;
            for (int k = 0; k < IN_DIM; k += 4) {
                #pragma unroll
                for (int j = 0; j < 4; j++) {
                    float wj0 = __ldg(&W1[(k + j) * HID_DIM + cp]);
                    float wj1 = __ldg(&W1[(k + j) * HID_DIM + cp + 64]);
                    ull wp0 = f2pack(wj0, wj0), wp1 = f2pack(wj1, wj1);
                    ulonglong2 p0 = *reinterpret_cast<const ulonglong2*>(&sm[S_A + (k + j) * ASTRIDE + nb]);
                    ulonglong2 p1 = *reinterpret_cast<const ulonglong2*>(&sm[S_A + (k + j) * ASTRIDE + nb + 4]);
                    a0 = fma2(wp0, p0.x, a0); a1 = fma2(wp0, p0.y, a1);
                    a2 = fma2(wp0, p1.x, a2); a3 = fma2(wp0, p1.y, a3);
                    a4 = fma2(wp1, p0.x, a4); a5 = fma2(wp1, p0.y, a5);
                    a6 = fma2(wp1, p1.x, a6); a7 = fma2(wp1, p1.y, a7);
                }
            }
            float t0,t1,t2,t3,t4,t5,t6,t7;
            f2unpack(a0,t0,t1); f2unpack(a1,t2,t3); f2unpack(a2,t4,t5); f2unpack(a3,t6,t7);
            *reinterpret_cast<float4*>(&sm[S_T + cp * ASTRIDE + nb]) =
                make_float4(fmaxf(t0,0.f), fmaxf(t1,0.f), fmaxf(t2,0.f), fmaxf(t3,0.f));
            *reinterpret_cast<float4*>(&sm[S_T + cp * ASTRIDE + nb + 4]) =
                make_float4(fmaxf(t4,0.f), fmaxf(t5,0.f), fmaxf(t6,0.f), fmaxf(t7,0.f));
            f2unpack(a4,t0,t1); f2unpack(a5,t2,t3); f2unpack(a6,t4,t5); f2unpack(a7,t6,t7);
            *reinterpret_cast<float4*>(&sm[S_T + (cp + 64) * ASTRIDE + nb]) =
                make_float4(fmaxf(t0,0.f), fmaxf(t1,0.f), fmaxf(t2,0.f), fmaxf(t3,0.f));
            *reinterpret_cast<float4*>(&sm[S_T + (cp + 64) * ASTRIDE + nb + 4]) =
                make_float4(fmaxf(t4,0.f), fmaxf(t5,0.f), fmaxf(t6,0.f), fmaxf(t7,0.f));
        }
        __syncthreads();                       // T ready (A now dead)

        // ---- layer 2: 128 -> 128, relu; writes H (clobbers A region) ----
        {
            float bb0 = sm[S_B2 + cp], bb1v = sm[S_B2 + cp + 64];
            ull a0 = f2pack(bb0, bb0), a1 = a0, a2 = a0, a3 = a0;
            ull a4 = f2pack(bb1v, bb1v), a5 = a4, a6 = a4, a7 = a4;
            for (int k = 0; k < HID_DIM; k += 4) {
                float4 w0 = *reinterpret_cast<const float4*>(&sm[S_W2T + cp * WST + k]);
                float4 w1 = *reinterpret_cast<const float4*>(&sm[S_W2T + (cp + 64) * WST + k]);
                #pragma unroll
                for (int j = 0; j < 4; j++) {
                    float wj0 = (&w0.x)[j], wj1 = (&w1.x)[j];
                    ull wp0 = f2pack(wj0, wj0), wp1 = f2pack(wj1, wj1);
                    ulonglong2 p0 = *reinterpret_cast<const ulonglong2*>(&sm[S_T + (k + j) * ASTRIDE + nb]);
                    ulonglong2 p1 = *reinterpret_cast<const ulonglong2*>(&sm[S_T + (k + j) * ASTRIDE + nb + 4]);
                    a0 = fma2(wp0, p0.x, a0); a1 = fma2(wp0, p0.y, a1);
                    a2 = fma2(wp0, p1.x, a2); a3 = fma2(wp0, p1.y, a3);
                    a4 = fma2(wp1, p0.x, a4); a5 = fma2(wp1, p0.y, a5);
                    a6 = fma2(wp1, p1.x, a6); a7 = fma2(wp1, p1.y, a7);
                }
            }
            float t0,t1,t2,t3,t4,t5,t6,t7;
            f2unpack(a0,t0,t1); f2unpack(a1,t2,t3); f2unpack(a2,t4,t5); f2unpack(a3,t6,t7);
            *reinterpret_cast<float4*>(&sm[S_H + cp * ASTRIDE + nb]) =
                make_float4(fmaxf(t0,0.f), fmaxf(t1,0.f), fmaxf(t2,0.f), fmaxf(t3,0.f));
            *reinterpret_cast<float4*>(&sm[S_H + cp * ASTRIDE + nb + 4]) =
                make_float4(fmaxf(t4,0.f), fmaxf(t5,0.f), fmaxf(t6,0.f), fmaxf(t7,0.f));
            f2unpack(a4,t0,t1); f2unpack(a5,t2,t3); f2unpack(a6,t4,t5); f2unpack(a7,t6,t7);
            *reinterpret_cast<float4*>(&sm[S_H + (cp + 64) * ASTRIDE + nb]) =
                make_float4(fmaxf(t0,0.f), fmaxf(t1,0.f), fmaxf(t2,0.f), fmaxf(t3,0.f));
            *reinterpret_cast<float4*>(&sm[S_H + (cp + 64) * ASTRIDE + nb + 4]) =
                make_float4(fmaxf(t4,0.f), fmaxf(t5,0.f), fmaxf(t6,0.f), fmaxf(t7,0.f));
        }
        __syncthreads();                       // H ready

        // ---- projection: t = h @ W3 (128->40), 640 thr x 8 nodes ----------
        if (pact) {
            ull q0 = f2pack(0.f, 0.f), q1 = q0, q2 = q0, q3 = q0;
            for (int k = 0; k < HID_DIM; k += 4) {
                float4 w = *reinterpret_cast<const float4*>(&sm[S_W3T + pc * WST + k]);
                #pragma unroll
                for (int j = 0; j < 4; j++) {
                    float wj = (&w.x)[j];
                    ull wp = f2pack(wj, wj);
                    ulonglong2 p0 = *reinterpret_cast<const ulonglong2*>(&sm[S_H + (k + j) * ASTRIDE + pnb]);
                    ulonglong2 p1 = *reinterpret_cast<const ulonglong2*>(&sm[S_H + (k + j) * ASTRIDE + pnb + 4]);
                    q0 = fma2(wp, p0.x, q0); q1 = fma2(wp, p0.y, q1);
                    q2 = fma2(wp, p1.x, q2); q3 = fma2(wp, p1.y, q3);
                }
            }
            float t0,t1,t2,t3,t4,t5,t6,t7;
            f2unpack(q0,t0,t1); f2unpack(q1,t2,t3); f2unpack(q2,t4,t5); f2unpack(q3,t6,t7);
            int n0 = base + pnb;
            if (n0 + 7 < N_NODES) {
                g_t[(size_t)(n0 + 0) * OUT_DIM + pc] = t0;
                g_t[(size_t)(n0 + 1) * OUT_DIM + pc] = t1;
                g_t[(size_t)(n0 + 2) * OUT_DIM + pc] = t2;
                g_t[(size_t)(n0 + 3) * OUT_DIM + pc] = t3;
                g_t[(size_t)(n0 + 4) * OUT_DIM + pc] = t4;
                g_t[(size_t)(n0 + 5) * OUT_DIM + pc] = t5;
                g_t[(size_t)(n0 + 6) * OUT_DIM + pc] = t6;
                g_t[(size_t)(n0 + 7) * OUT_DIM + pc] = t7;
            } else {
                float tv[8] = {t0,t1,t2,t3,t4,t5,t6,t7};
                #pragma unroll
                for (int i = 0; i < 8; i++)
                    if (n0 + i < N_NODES) g_t[(size_t)(n0 + i) * OUT_DIM + pc] = tv[i];
            }
        }
        __syncthreads();                       // proj done before A clobbers H

        // ---- stage next tile into A (= low half of H) ---------------------
        int gn = g + gridDim.x;
        if (gn < NTILES) {
            for (int it = tid; it < 2048; it += 1024) {
                int n = it >> 4, k4 = (it & 15) * 4;
                int node = gn * TILE + n;
                float4 v = (node < N_NODES)
                    ? *reinterpret_cast<const float4*>(g_agg1 + (size_t)node * IN_DIM + k4)
                    : make_float4(0.f, 0.f, 0.f, 0.f);
                sm[S_A + (k4 + 0) * ASTRIDE + n] = v.x;
                sm[S_A + (k4 + 1) * ASTRIDE + n] = v.y;
                sm[S_A + (k4 + 2) * ASTRIDE + n] = v.z;
                sm[S_A + (k4 + 3) * ASTRIDE + n] = v.w;
            }
        }
    }
}

// ---------------- K-final2: gather2 + bias + relu + log_softmax -------------
__global__ void k_final2(const float* __restrict__ b3, float* __restrict__ out) {
    int w = (blockIdx.x * blockDim.x + threadIdx.x) >> 5;
    if (w >= N_NODES) return;
    int lane = threadIdx.x & 31;
    int p = lane / 10;
    int c = lane - p * 10;
    bool active = p < 3;
    int deg = min(g_deg[w], CAP);
    const int* row = g_csr + (size_t)w * CAP;

    float4 acc = make_float4(0.f, 0.f, 0.f, 0.f);
    if (p == 0)
        acc = *reinterpret_cast<const float4*>(g_t + (size_t)w * OUT_DIM + c * 4);

    #pragma unroll 3
    for (int j = 0; j < deg; j += 3) {
        if (active && j + p < deg) {
            int s = row[j + p];
            float4 v = *reinterpret_cast<const float4*>(
                g_t + (size_t)s * OUT_DIM + c * 4);
            acc.x += v.x; acc.y += v.y; acc.z += v.z; acc.w += v.w;
        }
    }

    float4 u;
    u.x = acc.x + __shfl_sync(0xffffffffu, acc.x, lane + 10)
                + __shfl_sync(0xffffffffu, acc.x, lane + 20);
    u.y = acc.y + __shfl_sync(0xffffffffu, acc.y, lane + 10)
                + __shfl_sync(0xffffffffu, acc.y, lane + 20);
    u.z = acc.z + __shfl_sync(0xffffffffu, acc.z, lane + 10)
                + __shfl_sync(0xffffffffu, acc.z, lane + 20);
    u.w = acc.w + __shfl_sync(0xffffffffu, acc.w, lane + 10)
                + __shfl_sync(0xffffffffu, acc.w, lane + 20);

    bool owner = lane < 10;
    float4 a = make_float4(-3.4e38f, -3.4e38f, -3.4e38f, -3.4e38f);
    if (owner) {
        float4 bv = *reinterpret_cast<const float4*>(b3 + c * 4);
        a.x = fmaxf(u.x + bv.x, 0.f);
        a.y = fmaxf(u.y + bv.y, 0.f);
        a.z = fmaxf(u.z + bv.z, 0.f);
        a.w = fmaxf(u.w + bv.w, 0.f);
    }

    float m = fmaxf(fmaxf(a.x, a.y), fmaxf(a.z, a.w));
    #pragma unroll
    for (int o = 16; o > 0; o >>= 1)
        m = fmaxf(m, __shfl_xor_sync(0xffffffffu, m, o));

    float s = owner ? (expf(a.x - m) + expf(a.y - m) +
                       expf(a.z - m) + expf(a.w - m)) : 0.f;
    #pragma unroll
    for (int o = 16; o > 0; o >>= 1)
        s += __shfl_xor_sync(0xffffffffu, s, o);

    float lse = m + logf(s);
    if (owner) {
        float4 r = make_float4(a.x - lse, a.y - lse, a.z - lse, a.w - lse);
        *reinterpret_cast<float4*>(out + (size_t)w * OUT_DIM + c * 4) = r;
    }
}

// ---------------- launch ----------------
extern "C" void kernel_launch(void* const* d_in, const int* in_sizes, int n_in,
                              void* d_out, int out_size) {
    const float* x  = (const float*)d_in[0];
    const void*  ei = d_in[1];
    const float* W1 = (const float*)d_in[2];
    const float* b1 = (const float*)d_in[3];
    const float* W2 = (const float*)d_in[4];
    const float* b2 = (const float*)d_in[5];
    const float* W3 = (const float*)d_in[6];
    const float* b3 = (const float*)d_in[7];
    float* out = (float*)d_out;

    static bool attr_set = false;
    if (!attr_set) {
        cudaFuncSetAttribute(k_mlp, cudaFuncAttributeMaxDynamicSharedMemorySize,
                             SMEM_BYTES);
        attr_set = true;
    }

    k_prep<<<(N_NODES + 255) / 256, 256>>>((const long long*)ei);
    k_build<<<(N_EDGES + 255) / 256, 256>>>(ei);
    k_gather1<<<(N_NODES * 32 + 255) / 256, 256>>>(x);
    k_mlp<<<148, 1024, SMEM_BYTES>>>(W1, b1, W2, b2, W3);
    k_final2<<<(N_NODES * 32 + 255) / 256, 256>>>(b3, out);
}